// round 1
// baseline (speedup 1.0000x reference)
#include <cuda_runtime.h>

// Involution2D on GB300 — round 1: fused fp32 FFMA2 pipeline.
//
// Problem constants
#define BB   4
#define HH_  128
#define WW_  128
#define CC   256
#define CR   64
#define KKG  144
#define FF   256
#define NPIX (BB*HH_*WW_)   // 65536

// Scratch (device globals — no allocation allowed in kernel_launch)
__device__ float g_w_buf[(size_t)NPIX * KKG];   // per-pixel dynamic weights [P][144]
__device__ float g_xi_buf[(size_t)NPIX * FF];   // initial mapping           [P][256]

using u64 = unsigned long long;

// fma.rn.f32x2: packed 2-wide fp32 FMA — 2x FFMA throughput on sm_103a
__device__ __forceinline__ void fma2(u64 &d, u64 a, u64 b) {
    asm("fma.rn.f32x2 %0, %1, %2, %0;" : "+l"(d) : "l"(a), "l"(b));
}
__device__ __forceinline__ u64 pack2(float x, float y) {
    u64 r;
    asm("mov.b64 %0, {%1, %2};" : "=l"(r)
        : "r"(__float_as_uint(x)), "r"(__float_as_uint(y)));
    return r;
}
__device__ __forceinline__ float2 unpack2(u64 v) {
    unsigned lo, hi;
    asm("mov.b64 {%0, %1}, %2;" : "=r"(lo), "=r"(hi) : "l"(v));
    return make_float2(__uint_as_float(lo), __uint_as_float(hi));
}

// ---------------- kernel 1: fused  r -> w  and  xi ----------------
// 64 pixels per CTA. Shared-memory float offsets:
#define XS_OFF   0                      // x tile   [64][260]  (260 pad: conflict-free LDS + aligned STS128)
#define WB_OFF   16640                  // 16384 floats: Wr (step2) / w-stage (step3) / Wi ping-pong (step4)
#define RS_OFF   (WB_OFF + 16384)       // r tile   [64][68]
#define WSS_OFF  (RS_OFF + 64*68)       // Ws       [64][144]
#define SC_OFF   (WSS_OFF + 64*144)     // BN scale [64]
#define SH_OFF   (SC_OFF + 64)          // BN shift [64]
#define SMEM1_FLOATS (SH_OFF + 64)      // 46720 floats = 186,880 B

__global__ void __launch_bounds__(256, 1)
k_fused(const float* __restrict__ x,    const float* __restrict__ Wr,
        const float* __restrict__ br,   const float* __restrict__ gamma,
        const float* __restrict__ beta, const float* __restrict__ mean,
        const float* __restrict__ var,  const float* __restrict__ Ws,
        const float* __restrict__ bs,   const float* __restrict__ Wi,
        const float* __restrict__ bi)
{
    extern __shared__ float sm[];
    float* xs  = sm + XS_OFF;
    float* wb  = sm + WB_OFF;
    float* rs  = sm + RS_OFF;
    float* wss = sm + WSS_OFF;
    float* sc  = sm + SC_OFF;
    float* sh  = sm + SH_OFF;

    const int t  = threadIdx.x;
    const int p0 = blockIdx.x * 64;

    // BN folding: r = relu(dot*scale + shift)
    if (t < 64) {
        float s = gamma[t] * rsqrtf(var[t] + 1e-3f);
        sc[t] = s;
        sh[t] = (br[t] - mean[t]) * s + beta[t];
    }
    // Ws -> smem (2304 float4)
    for (int i = t; i < 2304; i += 256)
        ((float4*)wss)[i] = ((const float4*)Ws)[i];
    // Wr -> smem (4096 float4)
    for (int i = t; i < 4096; i += 256)
        ((float4*)wb)[i] = ((const float4*)Wr)[i];
    // x tile -> smem, padded rows of 260
    for (int i = t; i < 4096; i += 256) {
        int px = i >> 6, c4 = i & 63;
        float4 v = ((const float4*)(x + (size_t)(p0 + px) * 256))[c4];
        *(float4*)&xs[px * 260 + c4 * 4] = v;
    }
    __syncthreads();

    const int pg  = t >> 4;        // 16 pixel groups of 4
    const int cg  = t & 15;        // 16 channel groups
    const int pxb = pg * 4;

    // ---- step 2: r = relu(BN(x @ Wr))   [64px x 64ch], thread = 4px x 4ch ----
    {
        const int chb = cg * 4;
        u64 acc0[4] = {0,0,0,0}, acc1[4] = {0,0,0,0};
        #pragma unroll 4
        for (int k = 0; k < 256; k++) {
            u64 b0 = *(const u64*)&wb[k * 64 + chb];
            u64 b1 = *(const u64*)&wb[k * 64 + chb + 2];
            #pragma unroll
            for (int i = 0; i < 4; i++) {
                float a = xs[(pxb + i) * 260 + k];
                u64 a2 = pack2(a, a);
                fma2(acc0[i], a2, b0);
                fma2(acc1[i], a2, b1);
            }
        }
        #pragma unroll
        for (int i = 0; i < 4; i++) {
            float2 v0 = unpack2(acc0[i]), v1 = unpack2(acc1[i]);
            float vv[4] = {v0.x, v0.y, v1.x, v1.y};
            #pragma unroll
            for (int j = 0; j < 4; j++) {
                int ch = chb + j;
                rs[(pxb + i) * 68 + ch] = fmaxf(fmaf(vv[j], sc[ch], sh[ch]), 0.f);
            }
        }
    }
    __syncthreads();

    // ---- step 3: w = r @ Ws + bs   [64px x 144ch], thread = 4px x 9ch ----
    {
        const int ch9 = cg * 9;
        u64 a3[4][4]; float a3s[4];
        #pragma unroll
        for (int i = 0; i < 4; i++) {
            a3s[i] = 0.f;
            #pragma unroll
            for (int j = 0; j < 4; j++) a3[i][j] = 0;
        }
        #pragma unroll 2
        for (int k = 0; k < 64; k++) {
            float wv[9];
            #pragma unroll
            for (int j = 0; j < 9; j++) wv[j] = wss[k * 144 + ch9 + j];
            u64 wp[4];
            #pragma unroll
            for (int j = 0; j < 4; j++) wp[j] = pack2(wv[2*j], wv[2*j+1]);
            #pragma unroll
            for (int i = 0; i < 4; i++) {
                float a = rs[(pxb + i) * 68 + k];
                u64 a2 = pack2(a, a);
                #pragma unroll
                for (int j = 0; j < 4; j++) fma2(a3[i][j], a2, wp[j]);
                a3s[i] = fmaf(a, wv[8], a3s[i]);
            }
        }
        float bsv[9];
        #pragma unroll
        for (int j = 0; j < 9; j++) bsv[j] = bs[ch9 + j];
        // stage into wb (Wr no longer needed) for coalesced store
        #pragma unroll
        for (int i = 0; i < 4; i++) {
            float* dst = &wb[(pxb + i) * 144 + ch9];
            #pragma unroll
            for (int j = 0; j < 4; j++) {
                float2 v = unpack2(a3[i][j]);
                dst[2*j]     = v.x + bsv[2*j];
                dst[2*j + 1] = v.y + bsv[2*j + 1];
            }
            dst[8] = a3s[i] + bsv[8];
        }
    }
    __syncthreads();
    {
        float4* gw = (float4*)(g_w_buf + (size_t)p0 * 144);
        for (int i = t; i < 2304; i += 256) gw[i] = ((float4*)wb)[i];
    }
    __syncthreads();

    // ---- step 4: xi = x @ Wi + bi   [64px x 256ch], thread = 4px x 16ch ----
    // ch mapping cg*2 + 32*j: conflict-free LDS64 AND coalesced float2 gmem stores.
    {
        const int chb2 = cg * 2;
        u64 acc[4][8];
        #pragma unroll
        for (int i = 0; i < 4; i++)
            #pragma unroll
            for (int j = 0; j < 8; j++) acc[i][j] = 0;

        // preload Wi chunk 0 (32 rows x 256) into buffer 0
        {
            const float4* src = (const float4*)Wi;
            float4* dst = (float4*)wb;
            #pragma unroll
            for (int j = 0; j < 8; j++) dst[t + j*256] = src[t + j*256];
        }
        __syncthreads();

        for (int kb = 0; kb < 8; kb++) {
            const float* wbk = wb + (kb & 1) * 8192;
            float4 nxt[8];
            if (kb < 7) {   // prefetch next chunk to registers (overlap with compute)
                const float4* src = (const float4*)(Wi + (size_t)(kb + 1) * 32 * 256);
                #pragma unroll
                for (int j = 0; j < 8; j++) nxt[j] = src[t + j*256];
            }
            #pragma unroll 2
            for (int k2 = 0; k2 < 32; k2++) {
                int k = kb * 32 + k2;
                u64 bb[8];
                #pragma unroll
                for (int j = 0; j < 8; j++)
                    bb[j] = *(const u64*)&wbk[k2 * 256 + chb2 + 32 * j];
                #pragma unroll
                for (int i = 0; i < 4; i++) {
                    float a = xs[(pxb + i) * 260 + k];
                    u64 a2 = pack2(a, a);
                    #pragma unroll
                    for (int j = 0; j < 8; j++) fma2(acc[i][j], a2, bb[j]);
                }
            }
            __syncthreads();
            if (kb < 7) {   // commit prefetched chunk to the other buffer
                float4* dst = (float4*)(wb + ((kb + 1) & 1) * 8192);
                #pragma unroll
                for (int j = 0; j < 8; j++) dst[t + j*256] = nxt[j];
                __syncthreads();
            }
        }

        #pragma unroll
        for (int j = 0; j < 8; j++) {
            int ch = chb2 + 32 * j;
            float b0 = bi[ch], b1 = bi[ch + 1];
            #pragma unroll
            for (int i = 0; i < 4; i++) {
                float2 v = unpack2(acc[i][j]);
                float2 o = make_float2(v.x + b0, v.y + b1);
                *(float2*)&g_xi_buf[(size_t)(p0 + pxb + i) * 256 + ch] = o;
            }
        }
    }
}

// ---------------- kernel 2: involution gather/reduce ----------------
// CTA = 16-pixel row segment. smem: xi halo [3][18][256] + w tile [16][144].
// For output channel o=(g,fr): 9 taps at flat = g*144+fr*9+kk ->
//   kpos = flat/256 (spatial offset), c = flat%256 (channel).
// Lane stride across o is 9 mod 32 (even across the kpos wrap: delta ≡ 9 mod 32)
// -> all 32 banks distinct -> conflict-free LDS. w[g,kk] broadcast across fr.
#define INV_SMEM_FLOATS (3*18*256 + 16*144)   // 13824 + 2304 = 16128

__global__ void __launch_bounds__(256)
k_inv(float* __restrict__ out)
{
    extern __shared__ float sm2[];
    float* xis = sm2;            // [54][256]
    float* wsm = sm2 + 13824;    // [16][144]

    const int t   = threadIdx.x;
    const int seg = blockIdx.x & 7;
    const int h   = (blockIdx.x >> 3) & 127;
    const int b   = blockIdx.x >> 10;
    const int w0  = seg * 16;
    const size_t prow = ((size_t)b * 128 + h) * 128;

    // dynamic weights for these 16 pixels
    {
        const float4* src = (const float4*)(g_w_buf + (prow + w0) * 144);
        for (int i = t; i < 576; i += 256) ((float4*)wsm)[i] = src[i];
    }
    // xi halo tile: rows h-1..h+1, cols w0-1..w0+16, zero-padded OOB
    for (int i = t; i < 3456; i += 256) {
        int pos = i >> 6, c4 = i & 63;
        int rr = pos / 18, cc = pos - rr * 18;
        int hhp = h - 1 + rr, wwp = w0 - 1 + cc;
        float4 v = make_float4(0.f, 0.f, 0.f, 0.f);
        if ((unsigned)hhp < 128u && (unsigned)wwp < 128u)
            v = ((const float4*)(g_xi_buf +
                 (((size_t)b * 128 + hhp) * 128 + wwp) * 256))[c4];
        *(float4*)&xis[pos * 256 + c4 * 4] = v;
    }
    __syncthreads();

    const int o  = t;                 // one output channel per thread
    const int g  = o >> 4;
    const int fb = g * 144 + (o & 15) * 9;
    int off[9];
    #pragma unroll
    for (int kk = 0; kk < 9; kk++) {
        int flat = fb + kk;
        int kpos = flat >> 8;
        int c    = flat & 255;
        int di   = kpos / 3, dj = kpos - di * 3;
        off[kk]  = (di * 18 + dj) * 256 + c;
    }

    for (int px = 0; px < 16; px++) {
        const float* wp = &wsm[px * 144 + g * 9];   // broadcast across 16 fr lanes
        const float* xb = &xis[px * 256];
        float acc = 0.f;
        #pragma unroll
        for (int kk = 0; kk < 9; kk++)
            acc = fmaf(wp[kk], xb[off[kk]], acc);
        out[(prow + w0 + px) * 256 + o] = acc;      // coalesced: lanes = consecutive o
    }
}

// ---------------- launch ----------------
extern "C" void kernel_launch(void* const* d_in, const int* in_sizes, int n_in,
                              void* d_out, int out_size)
{
    const float* x     = (const float*)d_in[0];
    const float* Wr    = (const float*)d_in[1];
    const float* br    = (const float*)d_in[2];
    const float* gamma = (const float*)d_in[3];
    const float* beta  = (const float*)d_in[4];
    const float* mean  = (const float*)d_in[5];
    const float* var   = (const float*)d_in[6];
    const float* Ws    = (const float*)d_in[7];
    const float* bs    = (const float*)d_in[8];
    const float* Wi    = (const float*)d_in[9];
    const float* bi    = (const float*)d_in[10];
    float* out = (float*)d_out;
    (void)in_sizes; (void)n_in; (void)out_size;

    const int smem1 = SMEM1_FLOATS * (int)sizeof(float);   // 186,880 B
    const int smem2 = INV_SMEM_FLOATS * (int)sizeof(float); // 64,512 B
    cudaFuncSetAttribute(k_fused, cudaFuncAttributeMaxDynamicSharedMemorySize, smem1);
    cudaFuncSetAttribute(k_inv,   cudaFuncAttributeMaxDynamicSharedMemorySize, smem2);

    k_fused<<<NPIX / 64, 256, smem1>>>(x, Wr, br, gamma, beta, mean, var,
                                       Ws, bs, Wi, bi);
    k_inv<<<NPIX / 16, 256, smem2>>>(out);
}

// round 5
// speedup vs baseline: 1.1247x; 1.1247x over previous
#include <cuda_runtime.h>
#include <cuda_bf16.h>
#include <cstdint>

// Involution2D on GB300 — round 5: round-4 design with k_prep indexing fix
// (i>>4/i&15 -> i>>6/i&63; the old loop overflowed smem and read Wi OOB,
// causing the IMA in rounds 3-4).

#define BB   4
#define HH_  128
#define WW_  128
#define CC   256
#define CR   64
#define KKG  144
#define FF   256
#define NPIX (BB*HH_*WW_)   // 65536

// Scratch — force 16B alignment (uint2/uint4 access paths)
__device__ __align__(16) float g_w_buf[(size_t)NPIX * KKG];
__device__ __align__(16) float g_xi_buf[(size_t)NPIX * FF];
__device__ __align__(16) unsigned int g_wiT_hi[256 * 128];      // WiT bf16x2 [f][c/2]
__device__ __align__(16) unsigned int g_wiT_lo[256 * 128];
__device__ __align__(16) unsigned int g_x_hi[(size_t)NPIX * 128]; // x bf16x2 [px][c/2]
__device__ __align__(16) unsigned int g_x_lo[(size_t)NPIX * 128];

using u64 = unsigned long long;

#define SW(o) ((o) ^ (((o) >> 3) & 0x70))

__device__ __forceinline__ uint32_t bf16x2_rn(float lo, float hi) {
    uint32_t r;
    asm("cvt.rn.bf16x2.f32 %0, %1, %2;" : "=r"(r) : "f"(hi), "f"(lo));
    return r;
}
__device__ __forceinline__ void ldsm4(uint32_t (&r)[4], const void* p) {
    uint32_t addr;
    asm("{ .reg .u64 t; cvta.to.shared.u64 t, %1; cvt.u32.u64 %0, t; }"
        : "=r"(addr) : "l"(p));
    asm volatile("ldmatrix.sync.aligned.m8n8.x4.shared.b16 {%0,%1,%2,%3}, [%4];"
                 : "=r"(r[0]), "=r"(r[1]), "=r"(r[2]), "=r"(r[3]) : "r"(addr));
}
__device__ __forceinline__ void mma16816(float (&d)[4], const uint32_t (&a)[4],
                                         uint32_t b0, uint32_t b1) {
    asm volatile(
        "mma.sync.aligned.m16n8k16.row.col.f32.bf16.bf16.f32 "
        "{%0,%1,%2,%3}, {%4,%5,%6,%7}, {%8,%9}, {%0,%1,%2,%3};"
        : "+f"(d[0]), "+f"(d[1]), "+f"(d[2]), "+f"(d[3])
        : "r"(a[0]), "r"(a[1]), "r"(a[2]), "r"(a[3]), "r"(b0), "r"(b1));
}

// fp32 FFMA2 helpers (k_rw)
__device__ __forceinline__ void fma2(u64 &d, u64 a, u64 b) {
    asm("fma.rn.f32x2 %0, %1, %2, %0;" : "+l"(d) : "l"(a), "l"(b));
}
__device__ __forceinline__ u64 pack2(float x, float y) {
    u64 r;
    asm("mov.b64 %0, {%1, %2};" : "=l"(r)
        : "r"(__float_as_uint(x)), "r"(__float_as_uint(y)));
    return r;
}
__device__ __forceinline__ float2 unpack2(u64 v) {
    unsigned lo, hi;
    asm("mov.b64 {%0, %1}, %2;" : "=r"(lo), "=r"(hi) : "l"(v));
    return make_float2(__uint_as_float(lo), __uint_as_float(hi));
}

// ---------------- prep: x -> bf16 hi/lo split ----------------
__global__ void __launch_bounds__(256)
k_prepx(const float* __restrict__ x)
{
    const int gid = blockIdx.x * 256 + threadIdx.x;
    const float4* xs = (const float4*)x;
    for (int i = gid; i < NPIX * 64; i += 262144) {
        float4 v = xs[i];
        uint32_t u0 = __float_as_uint(v.x), u1 = __float_as_uint(v.y);
        uint32_t u2 = __float_as_uint(v.z), u3 = __float_as_uint(v.w);
        uint2 hi = make_uint2(__byte_perm(u0, u1, 0x7632),
                              __byte_perm(u2, u3, 0x7632));
        float l0 = v.x - __uint_as_float(u0 & 0xFFFF0000u);
        float l1 = v.y - __uint_as_float(u1 & 0xFFFF0000u);
        float l2 = v.z - __uint_as_float(u2 & 0xFFFF0000u);
        float l3 = v.w - __uint_as_float(u3 & 0xFFFF0000u);
        uint2 lo = make_uint2(bf16x2_rn(l0, l1), bf16x2_rn(l2, l3));
        ((uint2*)g_x_hi)[i] = hi;
        ((uint2*)g_x_lo)[i] = lo;
    }
}

// ---------------- prep: WiT = transpose(Wi), bf16 hi/lo ----------------
__global__ void __launch_bounds__(256)
k_prep(const float* __restrict__ Wi)
{
    extern __shared__ float sp[];          // [64][260]
    const int t  = threadIdx.x;
    const int c0 = blockIdx.x * 64;
    for (int i = t; i < 4096; i += 256) {
        int cl = i >> 6, f4 = i & 63;      // FIXED: 64 rows x 64 float4
        float4 v = ((const float4*)(Wi + (size_t)(c0 + cl) * 256))[f4];
        *(float4*)&sp[cl * 260 + f4 * 4] = v;
    }
    __syncthreads();
    for (int i = t; i < 8192; i += 256) {
        int f = i >> 5, cp = i & 31;
        int cl = cp * 2;
        float a = sp[cl * 260 + f];
        float b = sp[(cl + 1) * 260 + f];
        uint32_t ua = __float_as_uint(a), ub = __float_as_uint(b);
        uint32_t hi = __byte_perm(ua, ub, 0x7632);
        float la = a - __uint_as_float(ua & 0xFFFF0000u);
        float lb = b - __uint_as_float(ub & 0xFFFF0000u);
        uint32_t lo = bf16x2_rn(la, lb);
        g_wiT_hi[f * 128 + (c0 >> 1) + cp] = hi;
        g_wiT_lo[f * 128 + (c0 >> 1) + cp] = lo;
    }
}

// ---------------- kernel: xi = x @ Wi + bi via mma.sync ----------------
// CTA tile M=64, N=256; K in 4 chunks of 64; synchronous smem fill; 8 warps
// = 2(M) x 4(N). smem: Ahi 8K | Alo 8K | Bhi 32K | Blo 32K = 80 KB, 2 CTA/SM.
#define XS_A_HI 0
#define XS_A_LO 8192
#define XS_B_HI 16384
#define XS_B_LO 49152
#define XS_SMEM 81920

__global__ void __launch_bounds__(256, 2)
k_xi_mma(const float* __restrict__ bi)
{
    extern __shared__ char smc[];
    const int t    = threadIdx.x;
    const int wid  = t >> 5;
    const int lane = t & 31;
    const int p0   = blockIdx.x * 64;
    const int wm   = wid >> 2;           // 0..1
    const int wn   = wid & 3;            // 0..3

    float acc[2][8][4];
    #pragma unroll
    for (int i = 0; i < 2; ++i)
        #pragma unroll
        for (int j = 0; j < 8; ++j)
            #pragma unroll
            for (int q = 0; q < 4; ++q) acc[i][j][q] = 0.f;

    const uint4* gxh = (const uint4*)g_x_hi;
    const uint4* gxl = (const uint4*)g_x_lo;
    const uint4* gbh = (const uint4*)g_wiT_hi;
    const uint4* gbl = (const uint4*)g_wiT_lo;

    const int lr   = lane & 15;          // ldmatrix row within 16
    const int lk   = (lane >> 4) * 16;   // k-half byte offset
    const int arow = wm * 32 + lr;
    const int brow = wn * 64 + lr;

    for (int kb = 0; kb < 4; ++kb) {
        if (kb) __syncthreads();         // protect previous chunk's reads
        // A: 64 rows x 8 x 16B, hi+lo  (px stride = 32 uint4)
        #pragma unroll
        for (int it = 0; it < 2; ++it) {
            int gi = t + it * 256;
            int row = gi >> 3, c = gi & 7;
            int src = (p0 + row) * 32 + kb * 8 + c;
            uint32_t d = SW(row * 128 + c * 16);
            *(uint4*)(smc + XS_A_HI + d) = gxh[src];
            *(uint4*)(smc + XS_A_LO + d) = gxl[src];
        }
        // B: 256 rows x 8 x 16B, hi+lo  (f stride = 32 uint4)
        #pragma unroll
        for (int it = 0; it < 8; ++it) {
            int gi = t + it * 256;
            int f = gi >> 3, c = gi & 7;
            int src = f * 32 + kb * 8 + c;
            uint32_t d = SW(f * 128 + c * 16);
            *(uint4*)(smc + XS_B_HI + d) = gbh[src];
            *(uint4*)(smc + XS_B_LO + d) = gbl[src];
        }
        __syncthreads();

        #pragma unroll
        for (int k16 = 0; k16 < 4; ++k16) {
            const int ko = k16 * 32 + lk;
            uint32_t ah[2][4], al[2][4];
            #pragma unroll
            for (int i = 0; i < 2; ++i) {
                ldsm4(ah[i], smc + XS_A_HI + SW((arow + i * 16) * 128 + ko));
                ldsm4(al[i], smc + XS_A_LO + SW((arow + i * 16) * 128 + ko));
            }
            #pragma unroll
            for (int j = 0; j < 4; ++j) {
                uint32_t bh[4], bl[4];
                ldsm4(bh, smc + XS_B_HI + SW((brow + j * 16) * 128 + ko));
                ldsm4(bl, smc + XS_B_LO + SW((brow + j * 16) * 128 + ko));
                #pragma unroll
                for (int i = 0; i < 2; ++i) {
                    mma16816(acc[i][2*j],   ah[i], bh[0], bh[2]);
                    mma16816(acc[i][2*j+1], ah[i], bh[1], bh[3]);
                    mma16816(acc[i][2*j],   al[i], bh[0], bh[2]);
                    mma16816(acc[i][2*j+1], al[i], bh[1], bh[3]);
                    mma16816(acc[i][2*j],   ah[i], bl[0], bl[2]);
                    mma16816(acc[i][2*j+1], ah[i], bl[1], bl[3]);
                }
            }
        }
    }

    // epilogue: float2 stores (+bias); quad lanes give contiguous 32B sectors
    const int g  = lane >> 2;
    const int t2 = (lane & 3) * 2;
    #pragma unroll
    for (int i = 0; i < 2; ++i) {
        const int m = p0 + wm * 32 + i * 16 + g;
        #pragma unroll
        for (int j = 0; j < 8; ++j) {
            const int n = wn * 64 + j * 8 + t2;
            float b0 = bi[n], b1 = bi[n + 1];
            *(float2*)&g_xi_buf[(size_t)m * 256 + n] =
                make_float2(acc[i][j][0] + b0, acc[i][j][1] + b1);
            *(float2*)&g_xi_buf[(size_t)(m + 8) * 256 + n] =
                make_float2(acc[i][j][2] + b0, acc[i][j][3] + b1);
        }
    }
}

// ---------------- kernel: r -> w  (fp32 FFMA2) ----------------
#define XS_OFF   0
#define WB_OFF   16640
#define RS_OFF   (WB_OFF + 16384)
#define WSS_OFF  (RS_OFF + 64*68)
#define SC_OFF   (WSS_OFF + 64*144)
#define SH_OFF   (SC_OFF + 64)
#define SMEM1_FLOATS (SH_OFF + 64)

__global__ void __launch_bounds__(256, 1)
k_rw(const float* __restrict__ x,    const float* __restrict__ Wr,
     const float* __restrict__ br,   const float* __restrict__ gamma,
     const float* __restrict__ beta, const float* __restrict__ mean,
     const float* __restrict__ var,  const float* __restrict__ Ws,
     const float* __restrict__ bs)
{
    extern __shared__ float sm[];
    float* xs  = sm + XS_OFF;
    float* wb  = sm + WB_OFF;
    float* rs  = sm + RS_OFF;
    float* wss = sm + WSS_OFF;
    float* sc  = sm + SC_OFF;
    float* sh  = sm + SH_OFF;

    const int t  = threadIdx.x;
    const int p0 = blockIdx.x * 64;

    if (t < 64) {
        float s = gamma[t] * rsqrtf(var[t] + 1e-3f);
        sc[t] = s;
        sh[t] = (br[t] - mean[t]) * s + beta[t];
    }
    for (int i = t; i < 2304; i += 256)
        ((float4*)wss)[i] = ((const float4*)Ws)[i];
    for (int i = t; i < 4096; i += 256)
        ((float4*)wb)[i] = ((const float4*)Wr)[i];
    for (int i = t; i < 4096; i += 256) {
        int px = i >> 6, c4 = i & 63;
        float4 v = ((const float4*)(x + (size_t)(p0 + px) * 256))[c4];
        *(float4*)&xs[px * 260 + c4 * 4] = v;
    }
    __syncthreads();

    const int pg  = t >> 4;
    const int cg  = t & 15;
    const int pxb = pg * 4;

    // r = relu(BN(x @ Wr))
    {
        const int chb = cg * 4;
        u64 acc0[4] = {0,0,0,0}, acc1[4] = {0,0,0,0};
        #pragma unroll 4
        for (int k = 0; k < 256; k++) {
            u64 b0 = *(const u64*)&wb[k * 64 + chb];
            u64 b1 = *(const u64*)&wb[k * 64 + chb + 2];
            #pragma unroll
            for (int i = 0; i < 4; i++) {
                float a = xs[(pxb + i) * 260 + k];
                u64 a2 = pack2(a, a);
                fma2(acc0[i], a2, b0);
                fma2(acc1[i], a2, b1);
            }
        }
        #pragma unroll
        for (int i = 0; i < 4; i++) {
            float2 v0 = unpack2(acc0[i]), v1 = unpack2(acc1[i]);
            float vv[4] = {v0.x, v0.y, v1.x, v1.y};
            #pragma unroll
            for (int j = 0; j < 4; j++) {
                int ch = chb + j;
                rs[(pxb + i) * 68 + ch] = fmaxf(fmaf(vv[j], sc[ch], sh[ch]), 0.f);
            }
        }
    }
    __syncthreads();

    // w = r @ Ws + bs
    {
        const int ch9 = cg * 9;
        u64 a3[4][4]; float a3s[4];
        #pragma unroll
        for (int i = 0; i < 4; i++) {
            a3s[i] = 0.f;
            #pragma unroll
            for (int j = 0; j < 4; j++) a3[i][j] = 0;
        }
        #pragma unroll 2
        for (int k = 0; k < 64; k++) {
            float wv[9];
            #pragma unroll
            for (int j = 0; j < 9; j++) wv[j] = wss[k * 144 + ch9 + j];
            u64 wp[4];
            #pragma unroll
            for (int j = 0; j < 4; j++) wp[j] = pack2(wv[2*j], wv[2*j+1]);
            #pragma unroll
            for (int i = 0; i < 4; i++) {
                float a = rs[(pxb + i) * 68 + k];
                u64 a2 = pack2(a, a);
                #pragma unroll
                for (int j = 0; j < 4; j++) fma2(a3[i][j], a2, wp[j]);
                a3s[i] = fmaf(a, wv[8], a3s[i]);
            }
        }
        float bsv[9];
        #pragma unroll
        for (int j = 0; j < 9; j++) bsv[j] = bs[ch9 + j];
        #pragma unroll
        for (int i = 0; i < 4; i++) {
            float* dst = &wb[(pxb + i) * 144 + ch9];
            #pragma unroll
            for (int j = 0; j < 4; j++) {
                float2 v = unpack2(a3[i][j]);
                dst[2*j]     = v.x + bsv[2*j];
                dst[2*j + 1] = v.y + bsv[2*j + 1];
            }
            dst[8] = a3s[i] + bsv[8];
        }
    }
    __syncthreads();
    {
        float4* gw = (float4*)(g_w_buf + (size_t)p0 * 144);
        for (int i = t; i < 2304; i += 256) gw[i] = ((float4*)wb)[i];
    }
}

// ---------------- kernel: involution gather/reduce ----------------
#define INV_SMEM_FLOATS (3*18*256 + 16*144)

__global__ void __launch_bounds__(256)
k_inv(float* __restrict__ out)
{
    extern __shared__ float sm2[];
    float* xis = sm2;
    float* wsm = sm2 + 13824;

    const int t   = threadIdx.x;
    const int seg = blockIdx.x & 7;
    const int h   = (blockIdx.x >> 3) & 127;
    const int b   = blockIdx.x >> 10;
    const int w0  = seg * 16;
    const size_t prow = ((size_t)b * 128 + h) * 128;

    {
        const float4* src = (const float4*)(g_w_buf + (prow + w0) * 144);
        for (int i = t; i < 576; i += 256) ((float4*)wsm)[i] = src[i];
    }
    for (int i = t; i < 3456; i += 256) {
        int pos = i >> 6, c4 = i & 63;
        int rr = pos / 18, cc = pos - rr * 18;
        int hhp = h - 1 + rr, wwp = w0 - 1 + cc;
        float4 v = make_float4(0.f, 0.f, 0.f, 0.f);
        if ((unsigned)hhp < 128u && (unsigned)wwp < 128u)
            v = ((const float4*)(g_xi_buf +
                 (((size_t)b * 128 + hhp) * 128 + wwp) * 256))[c4];
        *(float4*)&xis[pos * 256 + c4 * 4] = v;
    }
    __syncthreads();

    const int o  = t;
    const int g  = o >> 4;
    const int fb = g * 144 + (o & 15) * 9;
    int off[9];
    #pragma unroll
    for (int kk = 0; kk < 9; kk++) {
        int flat = fb + kk;
        int kpos = flat >> 8;
        int c    = flat & 255;
        int di   = kpos / 3, dj = kpos - di * 3;
        off[kk]  = (di * 18 + dj) * 256 + c;
    }

    for (int px = 0; px < 16; px++) {
        const float* wp = &wsm[px * 144 + g * 9];
        const float* xb = &xis[px * 256];
        float acc = 0.f;
        #pragma unroll
        for (int kk = 0; kk < 9; kk++)
            acc = fmaf(wp[kk], xb[off[kk]], acc);
        out[(prow + w0 + px) * 256 + o] = acc;
    }
}

// ---------------- launch ----------------
extern "C" void kernel_launch(void* const* d_in, const int* in_sizes, int n_in,
                              void* d_out, int out_size)
{
    const float* x     = (const float*)d_in[0];
    const float* Wr    = (const float*)d_in[1];
    const float* br    = (const float*)d_in[2];
    const float* gamma = (const float*)d_in[3];
    const float* beta  = (const float*)d_in[4];
    const float* mean  = (const float*)d_in[5];
    const float* var   = (const float*)d_in[6];
    const float* Ws    = (const float*)d_in[7];
    const float* bs    = (const float*)d_in[8];
    const float* Wi    = (const float*)d_in[9];
    const float* bi    = (const float*)d_in[10];
    float* out = (float*)d_out;
    (void)in_sizes; (void)n_in; (void)out_size;

    const int smemP = 64 * 260 * (int)sizeof(float);          // 66,560
    const int smemX = XS_SMEM;                                 // 81,920
    const int smem1 = SMEM1_FLOATS * (int)sizeof(float);       // 186,880
    const int smem2 = INV_SMEM_FLOATS * (int)sizeof(float);    // 64,512
    cudaFuncSetAttribute(k_prep,   cudaFuncAttributeMaxDynamicSharedMemorySize, smemP);
    cudaFuncSetAttribute(k_xi_mma, cudaFuncAttributeMaxDynamicSharedMemorySize, smemX);
    cudaFuncSetAttribute(k_rw,     cudaFuncAttributeMaxDynamicSharedMemorySize, smem1);
    cudaFuncSetAttribute(k_inv,    cudaFuncAttributeMaxDynamicSharedMemorySize, smem2);

    k_prepx <<<1024,       256>>>(x);
    k_prep  <<<4,          256, smemP>>>(Wi);
    k_xi_mma<<<NPIX / 64,  256, smemX>>>(bi);
    k_rw    <<<NPIX / 64,  256, smem1>>>(x, Wr, br, gamma, beta, mean, var, Ws, bs);
    k_inv   <<<NPIX / 16,  256, smem2>>>(out);
}

// round 6
// speedup vs baseline: 1.5668x; 1.3930x over previous
#include <cuda_runtime.h>
#include <cuda_bf16.h>
#include <cstdint>

// Involution2D on GB300 — round 6: ALL GEMMs on mma.sync bf16 hi/lo.
//   k_prepx : x -> g_x_hi/lo            (bf16x2 split)
//   k_prep  : Wi -> WiT hi/lo
//   k_prepw_r / k_prepw_s : Wr, Ws -> transposed hi/lo
//   k_xi_mma: xi = x@Wi + bi            (round-5 proven)
//   k_rw_mma: r = relu(BN(x@Wr)); w = r@Ws + bs   (NEW, replaces 183us k_rw)
//   k_inv   : involution gather/reduce

#define BB   4
#define HH_  128
#define WW_  128
#define CC   256
#define CR   64
#define KKG  144
#define FF   256
#define NPIX (BB*HH_*WW_)   // 65536

__device__ __align__(16) float g_w_buf[(size_t)NPIX * KKG];
__device__ __align__(16) float g_xi_buf[(size_t)NPIX * FF];
__device__ __align__(16) unsigned int g_wiT_hi[256 * 128];       // [f][c/2]
__device__ __align__(16) unsigned int g_wiT_lo[256 * 128];
__device__ __align__(16) unsigned int g_wrT_hi[64 * 128];        // [n][c/2]
__device__ __align__(16) unsigned int g_wrT_lo[64 * 128];
__device__ __align__(16) unsigned int g_wsT_hi[144 * 32];        // [f][k/2]
__device__ __align__(16) unsigned int g_wsT_lo[144 * 32];
__device__ __align__(16) unsigned int g_x_hi[(size_t)NPIX * 128]; // [px][c/2]
__device__ __align__(16) unsigned int g_x_lo[(size_t)NPIX * 128];

#define SW(o) ((o) ^ (((o) >> 3) & 0x70))

__device__ __forceinline__ uint32_t bf16x2_rn(float lo, float hi) {
    uint32_t r;
    asm("cvt.rn.bf16x2.f32 %0, %1, %2;" : "=r"(r) : "f"(hi), "f"(lo));
    return r;
}
__device__ __forceinline__ void ldsm4(uint32_t (&r)[4], const void* p) {
    uint32_t addr;
    asm("{ .reg .u64 t; cvta.to.shared.u64 t, %1; cvt.u32.u64 %0, t; }"
        : "=r"(addr) : "l"(p));
    asm volatile("ldmatrix.sync.aligned.m8n8.x4.shared.b16 {%0,%1,%2,%3}, [%4];"
                 : "=r"(r[0]), "=r"(r[1]), "=r"(r[2]), "=r"(r[3]) : "r"(addr));
}
__device__ __forceinline__ void mma16816(float (&d)[4], const uint32_t (&a)[4],
                                         uint32_t b0, uint32_t b1) {
    asm volatile(
        "mma.sync.aligned.m16n8k16.row.col.f32.bf16.bf16.f32 "
        "{%0,%1,%2,%3}, {%4,%5,%6,%7}, {%8,%9}, {%0,%1,%2,%3};"
        : "+f"(d[0]), "+f"(d[1]), "+f"(d[2]), "+f"(d[3])
        : "r"(a[0]), "r"(a[1]), "r"(a[2]), "r"(a[3]), "r"(b0), "r"(b1));
}

// ---------------- prep: x -> bf16 hi/lo split ----------------
__global__ void __launch_bounds__(256)
k_prepx(const float* __restrict__ x)
{
    const int gid = blockIdx.x * 256 + threadIdx.x;
    const float4* xs = (const float4*)x;
    for (int i = gid; i < NPIX * 64; i += 262144) {
        float4 v = xs[i];
        uint32_t u0 = __float_as_uint(v.x), u1 = __float_as_uint(v.y);
        uint32_t u2 = __float_as_uint(v.z), u3 = __float_as_uint(v.w);
        uint2 hi = make_uint2(__byte_perm(u0, u1, 0x7632),
                              __byte_perm(u2, u3, 0x7632));
        float l0 = v.x - __uint_as_float(u0 & 0xFFFF0000u);
        float l1 = v.y - __uint_as_float(u1 & 0xFFFF0000u);
        float l2 = v.z - __uint_as_float(u2 & 0xFFFF0000u);
        float l3 = v.w - __uint_as_float(u3 & 0xFFFF0000u);
        uint2 lo = make_uint2(bf16x2_rn(l0, l1), bf16x2_rn(l2, l3));
        ((uint2*)g_x_hi)[i] = hi;
        ((uint2*)g_x_lo)[i] = lo;
    }
}

// ---------------- prep: WiT (transpose + hi/lo) ----------------
__global__ void __launch_bounds__(256)
k_prep(const float* __restrict__ Wi)
{
    extern __shared__ float sp[];          // [64][260]
    const int t  = threadIdx.x;
    const int c0 = blockIdx.x * 64;
    for (int i = t; i < 4096; i += 256) {
        int cl = i >> 6, f4 = i & 63;
        float4 v = ((const float4*)(Wi + (size_t)(c0 + cl) * 256))[f4];
        *(float4*)&sp[cl * 260 + f4 * 4] = v;
    }
    __syncthreads();
    for (int i = t; i < 8192; i += 256) {
        int f = i >> 5, cp = i & 31;
        int cl = cp * 2;
        float a = sp[cl * 260 + f];
        float b = sp[(cl + 1) * 260 + f];
        uint32_t ua = __float_as_uint(a), ub = __float_as_uint(b);
        uint32_t hi = __byte_perm(ua, ub, 0x7632);
        float la = a - __uint_as_float(ua & 0xFFFF0000u);
        float lb = b - __uint_as_float(ub & 0xFFFF0000u);
        g_wiT_hi[f * 128 + (c0 >> 1) + cp] = hi;
        g_wiT_lo[f * 128 + (c0 >> 1) + cp] = bf16x2_rn(la, lb);
    }
}

// ---------------- prep: WrT [64][256] hi/lo (Wr is [256][64]) ----------------
__global__ void __launch_bounds__(256)
k_prepw_r(const float* __restrict__ Wr)
{
    extern __shared__ float sp[];          // [256][68]
    const int t = threadIdx.x;
    for (int i = t; i < 4096; i += 256) {  // 256 rows x 16 float4
        int row = i >> 4, c4 = i & 15;
        float4 v = ((const float4*)(Wr + (size_t)row * 64))[c4];
        *(float4*)&sp[row * 68 + c4 * 4] = v;
    }
    __syncthreads();
    for (int i = t; i < 8192; i += 256) {  // 64 n x 128 k-pairs
        int n = i >> 7, kp = i & 127;
        float a = sp[(2 * kp) * 68 + n];
        float b = sp[(2 * kp + 1) * 68 + n];
        uint32_t ua = __float_as_uint(a), ub = __float_as_uint(b);
        uint32_t hi = __byte_perm(ua, ub, 0x7632);
        float la = a - __uint_as_float(ua & 0xFFFF0000u);
        float lb = b - __uint_as_float(ub & 0xFFFF0000u);
        g_wrT_hi[n * 128 + kp] = hi;
        g_wrT_lo[n * 128 + kp] = bf16x2_rn(la, lb);
    }
}

// ---------------- prep: WsT [144][64] hi/lo (Ws is [64][144]) ----------------
__global__ void __launch_bounds__(256)
k_prepw_s(const float* __restrict__ Ws)
{
    extern __shared__ float sp[];          // [64][148]
    const int t = threadIdx.x;
    for (int i = t; i < 9216; i += 256) {
        int row = i / 144, c = i - row * 144;
        sp[row * 148 + c] = Ws[i];
    }
    __syncthreads();
    for (int i = t; i < 4608; i += 256) {  // 144 f x 32 k-pairs
        int f = i >> 5, kp = i & 31;
        float a = sp[(2 * kp) * 148 + f];
        float b = sp[(2 * kp + 1) * 148 + f];
        uint32_t ua = __float_as_uint(a), ub = __float_as_uint(b);
        uint32_t hi = __byte_perm(ua, ub, 0x7632);
        float la = a - __uint_as_float(ua & 0xFFFF0000u);
        float lb = b - __uint_as_float(ub & 0xFFFF0000u);
        g_wsT_hi[f * 32 + kp] = hi;
        g_wsT_lo[f * 32 + kp] = bf16x2_rn(la, lb);
    }
}

// ---------------- kernel: xi = x @ Wi + bi via mma.sync (round-5) ----------------
#define XS_A_HI 0
#define XS_A_LO 8192
#define XS_B_HI 16384
#define XS_B_LO 49152
#define XS_SMEM 81920

__global__ void __launch_bounds__(256, 2)
k_xi_mma(const float* __restrict__ bi)
{
    extern __shared__ char smc[];
    const int t    = threadIdx.x;
    const int wid  = t >> 5;
    const int lane = t & 31;
    const int p0   = blockIdx.x * 64;
    const int wm   = wid >> 2;
    const int wn   = wid & 3;

    float acc[2][8][4];
    #pragma unroll
    for (int i = 0; i < 2; ++i)
        #pragma unroll
        for (int j = 0; j < 8; ++j)
            #pragma unroll
            for (int q = 0; q < 4; ++q) acc[i][j][q] = 0.f;

    const uint4* gxh = (const uint4*)g_x_hi;
    const uint4* gxl = (const uint4*)g_x_lo;
    const uint4* gbh = (const uint4*)g_wiT_hi;
    const uint4* gbl = (const uint4*)g_wiT_lo;

    const int lr   = lane & 15;
    const int lk   = (lane >> 4) * 16;
    const int arow = wm * 32 + lr;
    const int brow = wn * 64 + lr;

    for (int kb = 0; kb < 4; ++kb) {
        if (kb) __syncthreads();
        #pragma unroll
        for (int it = 0; it < 2; ++it) {
            int gi = t + it * 256;
            int row = gi >> 3, c = gi & 7;
            int src = (p0 + row) * 32 + kb * 8 + c;
            uint32_t d = SW(row * 128 + c * 16);
            *(uint4*)(smc + XS_A_HI + d) = gxh[src];
            *(uint4*)(smc + XS_A_LO + d) = gxl[src];
        }
        #pragma unroll
        for (int it = 0; it < 8; ++it) {
            int gi = t + it * 256;
            int f = gi >> 3, c = gi & 7;
            int src = f * 32 + kb * 8 + c;
            uint32_t d = SW(f * 128 + c * 16);
            *(uint4*)(smc + XS_B_HI + d) = gbh[src];
            *(uint4*)(smc + XS_B_LO + d) = gbl[src];
        }
        __syncthreads();

        #pragma unroll
        for (int k16 = 0; k16 < 4; ++k16) {
            const int ko = k16 * 32 + lk;
            uint32_t ah[2][4], al[2][4];
            #pragma unroll
            for (int i = 0; i < 2; ++i) {
                ldsm4(ah[i], smc + XS_A_HI + SW((arow + i * 16) * 128 + ko));
                ldsm4(al[i], smc + XS_A_LO + SW((arow + i * 16) * 128 + ko));
            }
            #pragma unroll
            for (int j = 0; j < 4; ++j) {
                uint32_t bh[4], bl[4];
                ldsm4(bh, smc + XS_B_HI + SW((brow + j * 16) * 128 + ko));
                ldsm4(bl, smc + XS_B_LO + SW((brow + j * 16) * 128 + ko));
                #pragma unroll
                for (int i = 0; i < 2; ++i) {
                    mma16816(acc[i][2*j],   ah[i], bh[0], bh[2]);
                    mma16816(acc[i][2*j+1], ah[i], bh[1], bh[3]);
                    mma16816(acc[i][2*j],   al[i], bh[0], bh[2]);
                    mma16816(acc[i][2*j+1], al[i], bh[1], bh[3]);
                    mma16816(acc[i][2*j],   ah[i], bl[0], bl[2]);
                    mma16816(acc[i][2*j+1], ah[i], bl[1], bl[3]);
                }
            }
        }
    }

    const int g  = lane >> 2;
    const int t2 = (lane & 3) * 2;
    #pragma unroll
    for (int i = 0; i < 2; ++i) {
        const int m = p0 + wm * 32 + i * 16 + g;
        #pragma unroll
        for (int j = 0; j < 8; ++j) {
            const int n = wn * 64 + j * 8 + t2;
            float b0 = bi[n], b1 = bi[n + 1];
            *(float2*)&g_xi_buf[(size_t)m * 256 + n] =
                make_float2(acc[i][j][0] + b0, acc[i][j][1] + b1);
            *(float2*)&g_xi_buf[(size_t)(m + 8) * 256 + n] =
                make_float2(acc[i][j][2] + b0, acc[i][j][3] + b1);
        }
    }
}

// ---------------- kernel: r+w fused on mma.sync ----------------
// M=64 px/CTA. GEMM1: x@Wr (N=64,K=256) -> BN+relu -> r hi/lo to smem.
// GEMM2: r@Ws (N=144,K=64) -> w to g_w_buf. 8 warps = 2(M) x 4(N).
#define RW_BWS_HI 0
#define RW_BWS_LO 18432
#define RW_SC     36864
#define RW_SH     37120
#define RW_A_HI   37376
#define RW_A_LO   45568
#define RW_B_HI   53760
#define RW_B_LO   61952
#define RW_R_HI   70144
#define RW_R_LO   78336
#define RW_SMEM   86528

__global__ void __launch_bounds__(256, 2)
k_rw_mma(const float* __restrict__ br,   const float* __restrict__ gamma,
         const float* __restrict__ beta, const float* __restrict__ mean,
         const float* __restrict__ var,  const float* __restrict__ bs)
{
    extern __shared__ char smc[];
    const int t    = threadIdx.x;
    const int wid  = t >> 5;
    const int lane = t & 31;
    const int p0   = blockIdx.x * 64;
    const int wm   = wid >> 2;
    const int wn   = wid & 3;

    // BN constants
    if (t < 64) {
        float s = gamma[t] * rsqrtf(var[t] + 1e-3f);
        *(float*)(smc + RW_SC + t * 4) = s;
        *(float*)(smc + RW_SH + t * 4) = (br[t] - mean[t]) * s + beta[t];
    }
    // resident WsT hi/lo [144][128B]
    {
        const uint4* sh = (const uint4*)g_wsT_hi;
        const uint4* sl = (const uint4*)g_wsT_lo;
        for (int i = t; i < 1152; i += 256) {
            int f = i >> 3, c = i & 7;
            uint32_t d = SW(f * 128 + c * 16);
            *(uint4*)(smc + RW_BWS_HI + d) = sh[i];
            *(uint4*)(smc + RW_BWS_LO + d) = sl[i];
        }
    }

    const int lr   = lane & 15;
    const int lk   = (lane >> 4) * 16;
    const int arow = wm * 32 + lr;

    // ---- GEMM1: acc1 = x @ Wr  (N=64: warp n16-block = wn) ----
    float acc1[2][2][4];
    #pragma unroll
    for (int i = 0; i < 2; ++i)
        #pragma unroll
        for (int j = 0; j < 2; ++j)
            #pragma unroll
            for (int q = 0; q < 4; ++q) acc1[i][j][q] = 0.f;

    const uint4* gxh = (const uint4*)g_x_hi;
    const uint4* gxl = (const uint4*)g_x_lo;
    const uint4* grh = (const uint4*)g_wrT_hi;
    const uint4* grl = (const uint4*)g_wrT_lo;
    const int brow1 = wn * 16 + lr;

    for (int kb = 0; kb < 4; ++kb) {
        if (kb) __syncthreads();
        #pragma unroll
        for (int it = 0; it < 2; ++it) {          // A: 64 rows x 8 granules
            int gi = t + it * 256;
            int row = gi >> 3, c = gi & 7;
            int src = (p0 + row) * 32 + kb * 8 + c;
            uint32_t d = SW(row * 128 + c * 16);
            *(uint4*)(smc + RW_A_HI + d) = gxh[src];
            *(uint4*)(smc + RW_A_LO + d) = gxl[src];
        }
        #pragma unroll
        for (int it = 0; it < 2; ++it) {          // B: 64 rows x 8 granules
            int gi = t + it * 256;
            int n = gi >> 3, c = gi & 7;
            int src = n * 32 + kb * 8 + c;
            uint32_t d = SW(n * 128 + c * 16);
            *(uint4*)(smc + RW_B_HI + d) = grh[src];
            *(uint4*)(smc + RW_B_LO + d) = grl[src];
        }
        __syncthreads();

        #pragma unroll
        for (int k16 = 0; k16 < 4; ++k16) {
            const int ko = k16 * 32 + lk;
            uint32_t ah[2][4], al[2][4], bh[4], bl[4];
            #pragma unroll
            for (int i = 0; i < 2; ++i) {
                ldsm4(ah[i], smc + RW_A_HI + SW((arow + i * 16) * 128 + ko));
                ldsm4(al[i], smc + RW_A_LO + SW((arow + i * 16) * 128 + ko));
            }
            ldsm4(bh, smc + RW_B_HI + SW(brow1 * 128 + ko));
            ldsm4(bl, smc + RW_B_LO + SW(brow1 * 128 + ko));
            #pragma unroll
            for (int i = 0; i < 2; ++i) {
                mma16816(acc1[i][0], ah[i], bh[0], bh[2]);
                mma16816(acc1[i][1], ah[i], bh[1], bh[3]);
                mma16816(acc1[i][0], al[i], bh[0], bh[2]);
                mma16816(acc1[i][1], al[i], bh[1], bh[3]);
                mma16816(acc1[i][0], ah[i], bl[0], bl[2]);
                mma16816(acc1[i][1], ah[i], bl[1], bl[3]);
            }
        }
    }
    __syncthreads();   // A/B buffers done; about to write r tiles

    // ---- epilogue 1: BN + relu, split r -> smem hi/lo bf16 ----
    {
        const int g  = lane >> 2;
        const int t2 = (lane & 3) * 2;
        #pragma unroll
        for (int i = 0; i < 2; ++i) {
            #pragma unroll
            for (int n8 = 0; n8 < 2; ++n8) {
                const int n0 = wn * 16 + n8 * 8 + t2;
                const float s0 = *(float*)(smc + RW_SC + n0 * 4);
                const float s1 = *(float*)(smc + RW_SC + (n0 + 1) * 4);
                const float h0 = *(float*)(smc + RW_SH + n0 * 4);
                const float h1 = *(float*)(smc + RW_SH + (n0 + 1) * 4);
                #pragma unroll
                for (int half = 0; half < 2; ++half) {
                    const int m = wm * 32 + i * 16 + g + half * 8;
                    float r0 = fmaxf(fmaf(acc1[i][n8][half * 2],     s0, h0), 0.f);
                    float r1 = fmaxf(fmaf(acc1[i][n8][half * 2 + 1], s1, h1), 0.f);
                    uint32_t u0 = __float_as_uint(r0), u1 = __float_as_uint(r1);
                    uint32_t hi = __byte_perm(u0, u1, 0x7632);
                    float l0 = r0 - __uint_as_float(u0 & 0xFFFF0000u);
                    float l1 = r1 - __uint_as_float(u1 & 0xFFFF0000u);
                    uint32_t d = SW(m * 128 + n0 * 2);
                    *(uint32_t*)(smc + RW_R_HI + d) = hi;
                    *(uint32_t*)(smc + RW_R_LO + d) = bf16x2_rn(l0, l1);
                }
            }
        }
    }
    __syncthreads();

    // ---- GEMM2: w = r @ Ws + bs  (N=144 = 9 n16-blocks, K=64) ----
    const int nblk = (wn == 3) ? 3 : 2;
    int blkid[3] = {wn, wn + 4, 8};
    float acc2[3][2][2][4];
    #pragma unroll
    for (int b = 0; b < 3; ++b)
        #pragma unroll
        for (int i = 0; i < 2; ++i)
            #pragma unroll
            for (int j = 0; j < 2; ++j)
                #pragma unroll
                for (int q = 0; q < 4; ++q) acc2[b][i][j][q] = 0.f;

    #pragma unroll
    for (int k16 = 0; k16 < 4; ++k16) {
        const int ko = k16 * 32 + lk;
        uint32_t ah[2][4], al[2][4];
        #pragma unroll
        for (int i = 0; i < 2; ++i) {
            ldsm4(ah[i], smc + RW_R_HI + SW((arow + i * 16) * 128 + ko));
            ldsm4(al[i], smc + RW_R_LO + SW((arow + i * 16) * 128 + ko));
        }
        for (int b = 0; b < nblk; ++b) {
            const int brow = blkid[b] * 16 + lr;
            uint32_t bh[4], bl[4];
            ldsm4(bh, smc + RW_BWS_HI + SW(brow * 128 + ko));
            ldsm4(bl, smc + RW_BWS_LO + SW(brow * 128 + ko));
            #pragma unroll
            for (int i = 0; i < 2; ++i) {
                mma16816(acc2[b][i][0], ah[i], bh[0], bh[2]);
                mma16816(acc2[b][i][1], ah[i], bh[1], bh[3]);
                mma16816(acc2[b][i][0], al[i], bh[0], bh[2]);
                mma16816(acc2[b][i][1], al[i], bh[1], bh[3]);
                mma16816(acc2[b][i][0], ah[i], bl[0], bl[2]);
                mma16816(acc2[b][i][1], ah[i], bl[1], bl[3]);
            }
        }
    }

    // ---- epilogue 2: w -> g_w_buf (+bs) ----
    {
        const int g  = lane >> 2;
        const int t2 = (lane & 3) * 2;
        for (int b = 0; b < nblk; ++b) {
            #pragma unroll
            for (int j = 0; j < 2; ++j) {
                const int n = blkid[b] * 16 + j * 8 + t2;
                const float b0 = bs[n], b1 = bs[n + 1];
                #pragma unroll
                for (int i = 0; i < 2; ++i) {
                    const int m = p0 + wm * 32 + i * 16 + g;
                    *(float2*)&g_w_buf[(size_t)m * 144 + n] =
                        make_float2(acc2[b][i][j][0] + b0, acc2[b][i][j][1] + b1);
                    *(float2*)&g_w_buf[(size_t)(m + 8) * 144 + n] =
                        make_float2(acc2[b][i][j][2] + b0, acc2[b][i][j][3] + b1);
                }
            }
        }
    }
}

// ---------------- kernel: involution gather/reduce ----------------
#define INV_SMEM_FLOATS (3*18*256 + 16*144)

__global__ void __launch_bounds__(256)
k_inv(float* __restrict__ out)
{
    extern __shared__ float sm2[];
    float* xis = sm2;
    float* wsm = sm2 + 13824;

    const int t   = threadIdx.x;
    const int seg = blockIdx.x & 7;
    const int h   = (blockIdx.x >> 3) & 127;
    const int b   = blockIdx.x >> 10;
    const int w0  = seg * 16;
    const size_t prow = ((size_t)b * 128 + h) * 128;

    {
        const float4* src = (const float4*)(g_w_buf + (prow + w0) * 144);
        for (int i = t; i < 576; i += 256) ((float4*)wsm)[i] = src[i];
    }
    for (int i = t; i < 3456; i += 256) {
        int pos = i >> 6, c4 = i & 63;
        int rr = pos / 18, cc = pos - rr * 18;
        int hhp = h - 1 + rr, wwp = w0 - 1 + cc;
        float4 v = make_float4(0.f, 0.f, 0.f, 0.f);
        if ((unsigned)hhp < 128u && (unsigned)wwp < 128u)
            v = ((const float4*)(g_xi_buf +
                 (((size_t)b * 128 + hhp) * 128 + wwp) * 256))[c4];
        *(float4*)&xis[pos * 256 + c4 * 4] = v;
    }
    __syncthreads();

    const int o  = t;
    const int g  = o >> 4;
    const int fb = g * 144 + (o & 15) * 9;
    int off[9];
    #pragma unroll
    for (int kk = 0; kk < 9; kk++) {
        int flat = fb + kk;
        int kpos = flat >> 8;
        int c    = flat & 255;
        int di   = kpos / 3, dj = kpos - di * 3;
        off[kk]  = (di * 18 + dj) * 256 + c;
    }

    for (int px = 0; px < 16; px++) {
        const float* wp = &wsm[px * 144 + g * 9];
        const float* xb = &xis[px * 256];
        float acc = 0.f;
        #pragma unroll
        for (int kk = 0; kk < 9; kk++)
            acc = fmaf(wp[kk], xb[off[kk]], acc);
        out[(prow + w0 + px) * 256 + o] = acc;
    }
}

// ---------------- launch ----------------
extern "C" void kernel_launch(void* const* d_in, const int* in_sizes, int n_in,
                              void* d_out, int out_size)
{
    const float* x     = (const float*)d_in[0];
    const float* Wr    = (const float*)d_in[1];
    const float* br    = (const float*)d_in[2];
    const float* gamma = (const float*)d_in[3];
    const float* beta  = (const float*)d_in[4];
    const float* mean  = (const float*)d_in[5];
    const float* var   = (const float*)d_in[6];
    const float* Ws    = (const float*)d_in[7];
    const float* bs    = (const float*)d_in[8];
    const float* Wi    = (const float*)d_in[9];
    const float* bi    = (const float*)d_in[10];
    float* out = (float*)d_out;
    (void)in_sizes; (void)n_in; (void)out_size;

    const int smemP  = 64 * 260 * (int)sizeof(float);          // 66,560
    const int smemPR = 256 * 68 * (int)sizeof(float);          // 69,632
    const int smemPS = 64 * 148 * (int)sizeof(float);          // 37,888
    const int smemX  = XS_SMEM;                                 // 81,920
    const int smemRW = RW_SMEM;                                 // 86,528
    const int smem2  = INV_SMEM_FLOATS * (int)sizeof(float);    // 64,512
    cudaFuncSetAttribute(k_prep,    cudaFuncAttributeMaxDynamicSharedMemorySize, smemP);
    cudaFuncSetAttribute(k_prepw_r, cudaFuncAttributeMaxDynamicSharedMemorySize, smemPR);
    cudaFuncSetAttribute(k_prepw_s, cudaFuncAttributeMaxDynamicSharedMemorySize, smemPS);
    cudaFuncSetAttribute(k_xi_mma,  cudaFuncAttributeMaxDynamicSharedMemorySize, smemX);
    cudaFuncSetAttribute(k_rw_mma,  cudaFuncAttributeMaxDynamicSharedMemorySize, smemRW);
    cudaFuncSetAttribute(k_inv,     cudaFuncAttributeMaxDynamicSharedMemorySize, smem2);

    k_prepx  <<<1024,      256>>>(x);
    k_prep   <<<4,         256, smemP>>>(Wi);
    k_prepw_r<<<1,         256, smemPR>>>(Wr);
    k_prepw_s<<<1,         256, smemPS>>>(Ws);
    k_xi_mma <<<NPIX / 64, 256, smemX>>>(bi);
    k_rw_mma <<<NPIX / 64, 256, smemRW>>>(br, gamma, beta, mean, var, bs);
    k_inv    <<<NPIX / 16, 256, smem2>>>(out);
}

// round 7
// speedup vs baseline: 2.2303x; 1.4235x over previous
#include <cuda_runtime.h>
#include <cuda_bf16.h>
#include <cstdint>

// Involution2D on GB300 — round 7: overlap everywhere.
//   k_prep_all: ALL prep (x split + 3 weight transposes) in ONE launch, no smem
//   k_xi_mma  : xi = x@Wi + bi, 2-stage cp.async pipeline (K=64 chunks)
//   k_rw_mma  : r/w GEMMs, full cp.async prefetch of all chunks
//   k_inv     : involution gather, cp.async tile loads with zfill OOB

#define BB   4
#define HH_  128
#define WW_  128
#define CC   256
#define CR   64
#define KKG  144
#define FF   256
#define NPIX (BB*HH_*WW_)   // 65536

__device__ __align__(16) float g_w_buf[(size_t)NPIX * KKG];
__device__ __align__(16) float g_xi_buf[(size_t)NPIX * FF];
__device__ __align__(16) unsigned int g_wiT_hi[256 * 128];       // [f][c/2]
__device__ __align__(16) unsigned int g_wiT_lo[256 * 128];
__device__ __align__(16) unsigned int g_wrT_hi[64 * 128];        // [n][c/2]
__device__ __align__(16) unsigned int g_wrT_lo[64 * 128];
__device__ __align__(16) unsigned int g_wsT_hi[144 * 32];        // [f][k/2]
__device__ __align__(16) unsigned int g_wsT_lo[144 * 32];
__device__ __align__(16) unsigned int g_x_hi[(size_t)NPIX * 128]; // [px][c/2]
__device__ __align__(16) unsigned int g_x_lo[(size_t)NPIX * 128];

#define SW(o) ((o) ^ (((o) >> 3) & 0x70))

__device__ __forceinline__ uint32_t smem_to_u32(const void* p) {
    uint32_t a;
    asm("{ .reg .u64 t; cvta.to.shared.u64 t, %1; cvt.u32.u64 %0, t; }"
        : "=r"(a) : "l"(p));
    return a;
}
__device__ __forceinline__ uint32_t bf16x2_rn(float lo, float hi) {
    uint32_t r;
    asm("cvt.rn.bf16x2.f32 %0, %1, %2;" : "=r"(r) : "f"(hi), "f"(lo));
    return r;
}
__device__ __forceinline__ void split2(float a, float b, uint32_t &hi, uint32_t &lo) {
    uint32_t ua = __float_as_uint(a), ub = __float_as_uint(b);
    hi = __byte_perm(ua, ub, 0x7632);
    lo = bf16x2_rn(a - __uint_as_float(ua & 0xFFFF0000u),
                   b - __uint_as_float(ub & 0xFFFF0000u));
}
__device__ __forceinline__ void cp_async16(uint32_t dst, const void* src) {
    asm volatile("{ .reg .u64 g; cvta.to.global.u64 g, %1;\n\t"
                 "cp.async.cg.shared.global [%0], [g], 16; }"
                 :: "r"(dst), "l"(src) : "memory");
}
__device__ __forceinline__ void cp_async16_z(uint32_t dst, const void* src, int sz) {
    asm volatile("{ .reg .u64 g; cvta.to.global.u64 g, %1;\n\t"
                 "cp.async.cg.shared.global [%0], [g], 16, %2; }"
                 :: "r"(dst), "l"(src), "r"(sz) : "memory");
}
#define CP_COMMIT() asm volatile("cp.async.commit_group;" ::: "memory")
#define CP_WAIT(n)  asm volatile("cp.async.wait_group %0;" :: "n"(n) : "memory")

__device__ __forceinline__ void ldsm4(uint32_t (&r)[4], const void* p) {
    uint32_t addr;
    asm("{ .reg .u64 t; cvta.to.shared.u64 t, %1; cvt.u32.u64 %0, t; }"
        : "=r"(addr) : "l"(p));
    asm volatile("ldmatrix.sync.aligned.m8n8.x4.shared.b16 {%0,%1,%2,%3}, [%4];"
                 : "=r"(r[0]), "=r"(r[1]), "=r"(r[2]), "=r"(r[3]) : "r"(addr));
}
__device__ __forceinline__ void mma16816(float (&d)[4], const uint32_t (&a)[4],
                                         uint32_t b0, uint32_t b1) {
    asm volatile(
        "mma.sync.aligned.m16n8k16.row.col.f32.bf16.bf16.f32 "
        "{%0,%1,%2,%3}, {%4,%5,%6,%7}, {%8,%9}, {%0,%1,%2,%3};"
        : "+f"(d[0]), "+f"(d[1]), "+f"(d[2]), "+f"(d[3])
        : "r"(a[0]), "r"(a[1]), "r"(a[2]), "r"(a[3]), "r"(b0), "r"(b1));
}

// ---------------- prep (single launch, all blocks concurrent) ----------------
// blocks [0,1024): x -> g_x_hi/lo
// blocks [1024,1040): Wi -> WiT hi/lo
// blocks [1040,1044): Wr -> WrT hi/lo
// blocks [1044,1046): Ws -> WsT hi/lo
__global__ void __launch_bounds__(256)
k_prep_all(const float* __restrict__ x,  const float* __restrict__ Wi,
           const float* __restrict__ Wr, const float* __restrict__ Ws)
{
    const int bid = blockIdx.x;
    const int t   = threadIdx.x;
    if (bid < 1024) {
        const int gid = bid * 256 + t;
        const float4* xs = (const float4*)x;
        #pragma unroll 4
        for (int i = gid; i < NPIX * 64; i += 262144) {
            float4 v = xs[i];
            uint32_t h0, l0, h1, l1;
            split2(v.x, v.y, h0, l0);
            split2(v.z, v.w, h1, l1);
            ((uint2*)g_x_hi)[i] = make_uint2(h0, h1);
            ((uint2*)g_x_lo)[i] = make_uint2(l0, l1);
        }
    } else if (bid < 1040) {
        const int idx = (bid - 1024) * 256 + t;
        for (int i = idx; i < 32768; i += 4096) {
            int f = i >> 7, cp = i & 127;
            float a = Wi[(size_t)(2 * cp)     * 256 + f];
            float b = Wi[(size_t)(2 * cp + 1) * 256 + f];
            uint32_t hi, lo;
            split2(a, b, hi, lo);
            g_wiT_hi[f * 128 + cp] = hi;
            g_wiT_lo[f * 128 + cp] = lo;
        }
    } else if (bid < 1044) {
        const int idx = (bid - 1040) * 256 + t;
        for (int i = idx; i < 8192; i += 1024) {
            int n = i >> 7, kp = i & 127;
            float a = Wr[(2 * kp)     * 64 + n];
            float b = Wr[(2 * kp + 1) * 64 + n];
            uint32_t hi, lo;
            split2(a, b, hi, lo);
            g_wrT_hi[n * 128 + kp] = hi;
            g_wrT_lo[n * 128 + kp] = lo;
        }
    } else {
        const int idx = (bid - 1044) * 256 + t;
        for (int i = idx; i < 4608; i += 512) {
            int f = i >> 5, kp = i & 31;
            float a = Ws[(2 * kp)     * 144 + f];
            float b = Ws[(2 * kp + 1) * 144 + f];
            uint32_t hi, lo;
            split2(a, b, hi, lo);
            g_wsT_hi[f * 32 + kp] = hi;
            g_wsT_lo[f * 32 + kp] = lo;
        }
    }
}

// ---------------- kernel: xi = x @ Wi + bi, 2-stage cp.async ----------------
#define XG_A_HI 0
#define XG_A_LO 8192
#define XG_B_HI 16384
#define XG_B_LO 49152
#define XG_BUF  81920
#define XG_SMEM (2 * XG_BUF)   // 163840

__device__ __forceinline__ void xi_issue_chunk(uint32_t sb, int buf, int kb,
                                               int p0, int t)
{
    const uint32_t base = sb + buf * XG_BUF;
    const uint4* gxh = (const uint4*)g_x_hi;
    const uint4* gxl = (const uint4*)g_x_lo;
    const uint4* gbh = (const uint4*)g_wiT_hi;
    const uint4* gbl = (const uint4*)g_wiT_lo;
    #pragma unroll
    for (int it = 0; it < 2; ++it) {          // A: 64 rows x 8 x 16B
        int gi = t + it * 256;
        int row = gi >> 3, c = gi & 7;
        int src = (p0 + row) * 32 + kb * 8 + c;
        uint32_t d = SW(row * 128 + c * 16);
        cp_async16(base + XG_A_HI + d, gxh + src);
        cp_async16(base + XG_A_LO + d, gxl + src);
    }
    #pragma unroll
    for (int it = 0; it < 8; ++it) {          // B: 256 rows x 8 x 16B
        int gi = t + it * 256;
        int f = gi >> 3, c = gi & 7;
        int src = f * 32 + kb * 8 + c;
        uint32_t d = SW(f * 128 + c * 16);
        cp_async16(base + XG_B_HI + d, gbh + src);
        cp_async16(base + XG_B_LO + d, gbl + src);
    }
}

__global__ void __launch_bounds__(256, 1)
k_xi_mma(const float* __restrict__ bi)
{
    extern __shared__ char smc[];
    const uint32_t sb = smem_to_u32(smc);
    const int t    = threadIdx.x;
    const int wid  = t >> 5;
    const int lane = t & 31;
    const int p0   = blockIdx.x * 64;
    const int wm   = wid >> 2;
    const int wn   = wid & 3;

    float acc[2][8][4];
    #pragma unroll
    for (int i = 0; i < 2; ++i)
        #pragma unroll
        for (int j = 0; j < 8; ++j)
            #pragma unroll
            for (int q = 0; q < 4; ++q) acc[i][j][q] = 0.f;

    xi_issue_chunk(sb, 0, 0, p0, t); CP_COMMIT();
    xi_issue_chunk(sb, 1, 1, p0, t); CP_COMMIT();

    const int lr   = lane & 15;
    const int lk   = (lane >> 4) * 16;
    const int arow = wm * 32 + lr;
    const int brow = wn * 64 + lr;

    for (int kb = 0; kb < 4; ++kb) {
        if (kb < 3) CP_WAIT(1); else CP_WAIT(0);
        __syncthreads();
        char* base = smc + (kb & 1) * XG_BUF;
        #pragma unroll
        for (int k16 = 0; k16 < 4; ++k16) {
            const int ko = k16 * 32 + lk;
            uint32_t ah[2][4], al[2][4];
            #pragma unroll
            for (int i = 0; i < 2; ++i) {
                ldsm4(ah[i], base + XG_A_HI + SW((arow + i * 16) * 128 + ko));
                ldsm4(al[i], base + XG_A_LO + SW((arow + i * 16) * 128 + ko));
            }
            #pragma unroll
            for (int j = 0; j < 4; ++j) {
                uint32_t bh[4], bl[4];
                ldsm4(bh, base + XG_B_HI + SW((brow + j * 16) * 128 + ko));
                ldsm4(bl, base + XG_B_LO + SW((brow + j * 16) * 128 + ko));
                #pragma unroll
                for (int i = 0; i < 2; ++i) {
                    mma16816(acc[i][2*j],   ah[i], bh[0], bh[2]);
                    mma16816(acc[i][2*j+1], ah[i], bh[1], bh[3]);
                    mma16816(acc[i][2*j],   al[i], bh[0], bh[2]);
                    mma16816(acc[i][2*j+1], al[i], bh[1], bh[3]);
                    mma16816(acc[i][2*j],   ah[i], bl[0], bl[2]);
                    mma16816(acc[i][2*j+1], ah[i], bl[1], bl[3]);
                }
            }
        }
        __syncthreads();                 // all reads done before overwrite
        if (kb + 2 < 4) { xi_issue_chunk(sb, kb & 1, kb + 2, p0, t); CP_COMMIT(); }
    }

    const int g  = lane >> 2;
    const int t2 = (lane & 3) * 2;
    #pragma unroll
    for (int i = 0; i < 2; ++i) {
        const int m = p0 + wm * 32 + i * 16 + g;
        #pragma unroll
        for (int j = 0; j < 8; ++j) {
            const int n = wn * 64 + j * 8 + t2;
            float b0 = bi[n], b1 = bi[n + 1];
            *(float2*)&g_xi_buf[(size_t)m * 256 + n] =
                make_float2(acc[i][j][0] + b0, acc[i][j][1] + b1);
            *(float2*)&g_xi_buf[(size_t)(m + 8) * 256 + n] =
                make_float2(acc[i][j][2] + b0, acc[i][j][3] + b1);
        }
    }
}

// ---------------- kernel: r+w fused, full cp.async prefetch ----------------
#define RW_WS_HI 0
#define RW_WS_LO 18432
#define RW_SC    36864
#define RW_SH    37120
#define RW_A_HI  37376     // 4 chunks x 8192
#define RW_A_LO  70144
#define RW_B_HI  102912
#define RW_B_LO  135680
#define RW_R_HI  168448
#define RW_R_LO  176640
#define RW_SMEM  184832

__global__ void __launch_bounds__(256, 1)
k_rw_mma(const float* __restrict__ br,   const float* __restrict__ gamma,
         const float* __restrict__ beta, const float* __restrict__ mean,
         const float* __restrict__ var,  const float* __restrict__ bs)
{
    extern __shared__ char smc[];
    const uint32_t sb = smem_to_u32(smc);
    const int t    = threadIdx.x;
    const int wid  = t >> 5;
    const int lane = t & 31;
    const int p0   = blockIdx.x * 64;
    const int wm   = wid >> 2;
    const int wn   = wid & 3;

    // group 0: resident WsT hi/lo
    {
        const uint4* sh = (const uint4*)g_wsT_hi;
        const uint4* sl = (const uint4*)g_wsT_lo;
        for (int i = t; i < 1152; i += 256) {
            int f = i >> 3, c = i & 7;
            uint32_t d = SW(f * 128 + c * 16);
            cp_async16(sb + RW_WS_HI + d, sh + i);
            cp_async16(sb + RW_WS_LO + d, sl + i);
        }
    }
    CP_COMMIT();
    // groups 1..4: all A/B chunks
    {
        const uint4* gxh = (const uint4*)g_x_hi;
        const uint4* gxl = (const uint4*)g_x_lo;
        const uint4* grh = (const uint4*)g_wrT_hi;
        const uint4* grl = (const uint4*)g_wrT_lo;
        #pragma unroll
        for (int kb = 0; kb < 4; ++kb) {
            #pragma unroll
            for (int it = 0; it < 2; ++it) {      // A: 64 rows x 8 x 16B
                int gi = t + it * 256;
                int row = gi >> 3, c = gi & 7;
                int src = (p0 + row) * 32 + kb * 8 + c;
                uint32_t d = kb * 8192 + SW(row * 128 + c * 16);
                cp_async16(sb + RW_A_HI + d, gxh + src);
                cp_async16(sb + RW_A_LO + d, gxl + src);
            }
            #pragma unroll
            for (int it = 0; it < 2; ++it) {      // B: 64 rows x 8 x 16B
                int gi = t + it * 256;
                int n = gi >> 3, c = gi & 7;
                int src = n * 32 + kb * 8 + c;
                uint32_t d = kb * 8192 + SW(n * 128 + c * 16);
                cp_async16(sb + RW_B_HI + d, grh + src);
                cp_async16(sb + RW_B_LO + d, grl + src);
            }
            CP_COMMIT();
        }
    }
    // BN constants (regular loads, visible after first barrier)
    if (t < 64) {
        float s = gamma[t] * rsqrtf(var[t] + 1e-3f);
        *(float*)(smc + RW_SC + t * 4) = s;
        *(float*)(smc + RW_SH + t * 4) = (br[t] - mean[t]) * s + beta[t];
    }

    const int lr   = lane & 15;
    const int lk   = (lane >> 4) * 16;
    const int arow = wm * 32 + lr;
    const int brow1 = wn * 16 + lr;

    // ---- GEMM1: x @ Wr  (N=64, K=256) ----
    float acc1[2][2][4];
    #pragma unroll
    for (int i = 0; i < 2; ++i)
        #pragma unroll
        for (int j = 0; j < 2; ++j)
            #pragma unroll
            for (int q = 0; q < 4; ++q) acc1[i][j][q] = 0.f;

    #pragma unroll
    for (int kb = 0; kb < 4; ++kb) {
        if      (kb == 0) CP_WAIT(3);
        else if (kb == 1) CP_WAIT(2);
        else if (kb == 2) CP_WAIT(1);
        else              CP_WAIT(0);
        __syncthreads();
        char* abase = smc + RW_A_HI + kb * 8192;
        char* albase = smc + RW_A_LO + kb * 8192;
        char* bbase = smc + RW_B_HI + kb * 8192;
        char* blbase = smc + RW_B_LO + kb * 8192;
        #pragma unroll
        for (int k16 = 0; k16 < 4; ++k16) {
            const int ko = k16 * 32 + lk;
            uint32_t ah[2][4], al[2][4], bh[4], bl[4];
            #pragma unroll
            for (int i = 0; i < 2; ++i) {
                ldsm4(ah[i], abase  + SW((arow + i * 16) * 128 + ko));
                ldsm4(al[i], albase + SW((arow + i * 16) * 128 + ko));
            }
            ldsm4(bh, bbase  + SW(brow1 * 128 + ko));
            ldsm4(bl, blbase + SW(brow1 * 128 + ko));
            #pragma unroll
            for (int i = 0; i < 2; ++i) {
                mma16816(acc1[i][0], ah[i], bh[0], bh[2]);
                mma16816(acc1[i][1], ah[i], bh[1], bh[3]);
                mma16816(acc1[i][0], al[i], bh[0], bh[2]);
                mma16816(acc1[i][1], al[i], bh[1], bh[3]);
                mma16816(acc1[i][0], ah[i], bl[0], bl[2]);
                mma16816(acc1[i][1], ah[i], bl[1], bl[3]);
            }
        }
    }

    // ---- epilogue 1: BN + relu, split r -> smem hi/lo ----
    {
        const int g  = lane >> 2;
        const int t2 = (lane & 3) * 2;
        #pragma unroll
        for (int i = 0; i < 2; ++i) {
            #pragma unroll
            for (int n8 = 0; n8 < 2; ++n8) {
                const int n0 = wn * 16 + n8 * 8 + t2;
                const float s0 = *(float*)(smc + RW_SC + n0 * 4);
                const float s1 = *(float*)(smc + RW_SC + (n0 + 1) * 4);
                const float h0 = *(float*)(smc + RW_SH + n0 * 4);
                const float h1 = *(float*)(smc + RW_SH + (n0 + 1) * 4);
                #pragma unroll
                for (int half = 0; half < 2; ++half) {
                    const int m = wm * 32 + i * 16 + g + half * 8;
                    float r0 = fmaxf(fmaf(acc1[i][n8][half * 2],     s0, h0), 0.f);
                    float r1 = fmaxf(fmaf(acc1[i][n8][half * 2 + 1], s1, h1), 0.f);
                    uint32_t hi, lo;
                    split2(r0, r1, hi, lo);
                    uint32_t d = SW(m * 128 + n0 * 2);
                    *(uint32_t*)(smc + RW_R_HI + d) = hi;
                    *(uint32_t*)(smc + RW_R_LO + d) = lo;
                }
            }
        }
    }
    __syncthreads();

    // ---- GEMM2: w = r @ Ws + bs  (N=144, K=64) ----
    const int nblk = (wn == 3) ? 3 : 2;
    int blkid[3] = {wn, wn + 4, 8};
    float acc2[3][2][2][4];
    #pragma unroll
    for (int b = 0; b < 3; ++b)
        #pragma unroll
        for (int i = 0; i < 2; ++i)
            #pragma unroll
            for (int j = 0; j < 2; ++j)
                #pragma unroll
                for (int q = 0; q < 4; ++q) acc2[b][i][j][q] = 0.f;

    #pragma unroll
    for (int k16 = 0; k16 < 4; ++k16) {
        const int ko = k16 * 32 + lk;
        uint32_t ah[2][4], al[2][4];
        #pragma unroll
        for (int i = 0; i < 2; ++i) {
            ldsm4(ah[i], smc + RW_R_HI + SW((arow + i * 16) * 128 + ko));
            ldsm4(al[i], smc + RW_R_LO + SW((arow + i * 16) * 128 + ko));
        }
        for (int b = 0; b < nblk; ++b) {
            const int brow = blkid[b] * 16 + lr;
            uint32_t bh[4], bl[4];
            ldsm4(bh, smc + RW_WS_HI + SW(brow * 128 + ko));
            ldsm4(bl, smc + RW_WS_LO + SW(brow * 128 + ko));
            #pragma unroll
            for (int i = 0; i < 2; ++i) {
                mma16816(acc2[b][i][0], ah[i], bh[0], bh[2]);
                mma16816(acc2[b][i][1], ah[i], bh[1], bh[3]);
                mma16816(acc2[b][i][0], al[i], bh[0], bh[2]);
                mma16816(acc2[b][i][1], al[i], bh[1], bh[3]);
                mma16816(acc2[b][i][0], ah[i], bl[0], bl[2]);
                mma16816(acc2[b][i][1], ah[i], bl[1], bl[3]);
            }
        }
    }

    // ---- epilogue 2: w -> g_w_buf (+bs) ----
    {
        const int g  = lane >> 2;
        const int t2 = (lane & 3) * 2;
        for (int b = 0; b < nblk; ++b) {
            #pragma unroll
            for (int j = 0; j < 2; ++j) {
                const int n = blkid[b] * 16 + j * 8 + t2;
                const float b0 = bs[n], b1 = bs[n + 1];
                #pragma unroll
                for (int i = 0; i < 2; ++i) {
                    const int m = p0 + wm * 32 + i * 16 + g;
                    *(float2*)&g_w_buf[(size_t)m * 144 + n] =
                        make_float2(acc2[b][i][j][0] + b0, acc2[b][i][j][1] + b1);
                    *(float2*)&g_w_buf[(size_t)(m + 8) * 144 + n] =
                        make_float2(acc2[b][i][j][2] + b0, acc2[b][i][j][3] + b1);
                }
            }
        }
    }
}

// ---------------- kernel: involution gather/reduce (cp.async loads) ----------------
#define INV_SMEM_FLOATS (3*18*256 + 16*144)

__global__ void __launch_bounds__(256)
k_inv(float* __restrict__ out)
{
    extern __shared__ float sm2[];
    float* xis = sm2;                       // [54][256]
    float* wsm = sm2 + 13824;               // [16][144]
    const uint32_t sb = smem_to_u32(sm2);

    const int t   = threadIdx.x;
    const int seg = blockIdx.x & 7;
    const int h   = (blockIdx.x >> 3) & 127;
    const int b   = blockIdx.x >> 10;
    const int w0  = seg * 16;
    const size_t prow = ((size_t)b * 128 + h) * 128;

    // dynamic weights (576 x 16B)
    {
        const uint4* src = (const uint4*)(g_w_buf + (prow + w0) * 144);
        for (int i = t; i < 576; i += 256)
            cp_async16(sb + 55296 + i * 16, src + i);
    }
    // xi halo tile, zfill for OOB
    for (int i = t; i < 3456; i += 256) {
        int pos = i >> 6, c4 = i & 63;
        int rr = pos / 18, cc = pos - rr * 18;
        int hhp = h - 1 + rr, wwp = w0 - 1 + cc;
        bool ok = ((unsigned)hhp < 128u) && ((unsigned)wwp < 128u);
        const uint4* s = ok
            ? (const uint4*)(g_xi_buf + (((size_t)b * 128 + hhp) * 128 + wwp) * 256) + c4
            : (const uint4*)g_xi_buf;
        cp_async16_z(sb + (uint32_t)(pos * 1024 + c4 * 16), s, ok ? 16 : 0);
    }
    CP_COMMIT();
    CP_WAIT(0);
    __syncthreads();

    const int o  = t;
    const int g  = o >> 4;
    const int fb = g * 144 + (o & 15) * 9;
    int off[9];
    #pragma unroll
    for (int kk = 0; kk < 9; kk++) {
        int flat = fb + kk;
        int kpos = flat >> 8;
        int c    = flat & 255;
        int di   = kpos / 3, dj = kpos - di * 3;
        off[kk]  = (di * 18 + dj) * 256 + c;
    }

    for (int px = 0; px < 16; px++) {
        const float* wp = &wsm[px * 144 + g * 9];
        const float* xb = &xis[px * 256];
        float acc = 0.f;
        #pragma unroll
        for (int kk = 0; kk < 9; kk++)
            acc = fmaf(wp[kk], xb[off[kk]], acc);
        out[(prow + w0 + px) * 256 + o] = acc;
    }
}

// ---------------- launch ----------------
extern "C" void kernel_launch(void* const* d_in, const int* in_sizes, int n_in,
                              void* d_out, int out_size)
{
    const float* x     = (const float*)d_in[0];
    const float* Wr    = (const float*)d_in[1];
    const float* br    = (const float*)d_in[2];
    const float* gamma = (const float*)d_in[3];
    const float* beta  = (const float*)d_in[4];
    const float* mean  = (const float*)d_in[5];
    const float* var   = (const float*)d_in[6];
    const float* Ws    = (const float*)d_in[7];
    const float* bs    = (const float*)d_in[8];
    const float* Wi    = (const float*)d_in[9];
    const float* bi    = (const float*)d_in[10];
    float* out = (float*)d_out;
    (void)in_sizes; (void)n_in; (void)out_size;

    const int smemX  = XG_SMEM;                                 // 163,840
    const int smemRW = RW_SMEM;                                 // 184,832
    const int smem2  = INV_SMEM_FLOATS * (int)sizeof(float);    // 64,512
    cudaFuncSetAttribute(k_xi_mma, cudaFuncAttributeMaxDynamicSharedMemorySize, smemX);
    cudaFuncSetAttribute(k_rw_mma, cudaFuncAttributeMaxDynamicSharedMemorySize, smemRW);
    cudaFuncSetAttribute(k_inv,    cudaFuncAttributeMaxDynamicSharedMemorySize, smem2);

    k_prep_all<<<1046,      256>>>(x, Wi, Wr, Ws);
    k_xi_mma  <<<NPIX / 64, 256, smemX>>>(bi);
    k_rw_mma  <<<NPIX / 64, 256, smemRW>>>(br, gamma, beta, mean, var, bs);
    k_inv     <<<NPIX / 16, 256, smem2>>>(out);
}